// round 9
// baseline (speedup 1.0000x reference)
#include <cuda_runtime.h>
#include <cstdint>

// ---------------- problem constants ----------------
constexpr int NN  = 38000;   // nodes
constexpr int IND = 64;      // input dim
constexpr int HID = 128;
constexpr int RR  = 8;       // relations
constexpr int EE  = 200000;  // edges per relation
constexpr int NR  = 60000;   // rows
constexpr int FF  = 19;      // features per row
constexpr int NC  = 10;      // classes

// ---------------- device scratch (static, no allocation) ----------------
__device__ float g_h0[(size_t)NN * HID];
__device__ float g_h1[(size_t)NN * HID];
__device__ float g_h2[(size_t)NN * HID];
__device__ float g_agg[(size_t)RR * NN * HID];      // 155.6 MB
__device__ float g_deg_out[RR * NN];
__device__ float g_deg_in[RR * NN];
__device__ float g_norm_s[RR * NN];
__device__ float g_norm_d[RR * NN];
__device__ float g_mean[(size_t)NR * HID];
__device__ float g_x1[(size_t)NR * HID];
__device__ float g_x2[(size_t)NR * HID];
__device__ int   g_mask_is_int;

// ---------------- packed f32x2 helpers ----------------
__device__ __forceinline__ unsigned long long pack_dup(float f) {
    unsigned long long u;
    asm("mov.b64 %0, {%1, %1};" : "=l"(u) : "f"(f));
    return u;
}
__device__ __forceinline__ void ffma2(unsigned long long& acc,
                                      unsigned long long a, unsigned long long b) {
    asm("fma.rn.f32x2 %0, %1, %2, %0;" : "+l"(acc) : "l"(a), "l"(b));
}
__device__ __forceinline__ void unpack2(unsigned long long p, float& lo, float& hi) {
    asm("mov.b64 {%0, %1}, %2;" : "=f"(lo), "=f"(hi) : "l"(p));
}

// ---------------- zero ----------------
__global__ void k_zero4(float4* p, long long n4) {
    long long i = (long long)blockIdx.x * blockDim.x + threadIdx.x;
    long long stride = (long long)gridDim.x * blockDim.x;
    float4 z = make_float4(0.f, 0.f, 0.f, 0.f);
    for (; i < n4; i += stride) p[i] = z;
}

// ---------------- mask dtype detection (bool stored as u8 vs i32) ----------
__global__ void k_detect_mask(const unsigned char* __restrict__ m) {
    __shared__ int cnt;
    if (threadIdx.x == 0) cnt = 0;
    __syncthreads();
    int local = 0;
    for (int i = threadIdx.x; i < 65536; i += blockDim.x) local += (m[i] != 0);
    atomicAdd(&cnt, local);
    __syncthreads();
    if (threadIdx.x == 0) g_mask_is_int = (cnt < 16384) ? 1 : 0;
}

// ---------------- degrees + norms ----------------
__global__ void k_deg(const int* __restrict__ src, const int* __restrict__ dst) {
    long long i = (long long)blockIdx.x * blockDim.x + threadIdx.x;
    if (i >= (long long)RR * EE) return;
    int r = (int)(i / EE);
    atomicAdd(&g_deg_out[r * NN + src[i]], 1.f);
    atomicAdd(&g_deg_in [r * NN + dst[i]], 1.f);
}
__global__ void k_norms() {
    int i = blockIdx.x * blockDim.x + threadIdx.x;
    if (i >= RR * NN) return;
    g_norm_s[i] = rsqrtf(fmaxf(g_deg_out[i], 1.f));
    g_norm_d[i] = rsqrtf(fmaxf(g_deg_in [i], 1.f));
}

// ---------------- edge aggregation: one warp per edge, float4 RED ----------------
// g_agg[r][dst] += h[src] * norm_s[r][src]
__global__ void k_agg(const float* __restrict__ h,
                      const int* __restrict__ src, const int* __restrict__ dst) {
    long long gtid = (long long)blockIdx.x * blockDim.x + threadIdx.x;
    long long w = gtid >> 5;
    if (w >= (long long)RR * EE) return;
    int lane = threadIdx.x & 31;
    int r = (int)(w / EE);
    int s = __ldg(&src[w]);
    int d = __ldg(&dst[w]);
    float sc = __ldg(&g_norm_s[(size_t)r * NN + s]);
    float4 v = __ldg((const float4*)(h + (size_t)s * HID) + lane);
    v.x *= sc; v.y *= sc; v.z *= sc; v.w *= sc;
    atomicAdd((float4*)(g_agg + ((size_t)r * NN + d) * HID) + lane, v);
}

// ---------------- FFMA2 GEMM: C[M][128] = epi(A'[M][K] @ B[K][128] + bias) ----
// BM=128, BN=128, BK=16, 128 threads, 8x16 per-thread micro-tile,
// accumulators packed as fp32x2 row-pairs -> fma.rn.f32x2 (2x FFMA throughput).
// LAYER mode: A' = implicit [NN][R*128] from g_agg with per-(r,row) norm_d
// scaling; bias = sum_r bias[r][:].
template <bool RELU, bool LAYER>
__global__ __launch_bounds__(128, 2)
void k_fgemm(const float* __restrict__ A, const float* __restrict__ B,
             const float* __restrict__ bias, float* __restrict__ C,
             int M, int K) {
    __shared__ __align__(16) float As[16][132];   // [k][m], 528B stride
    __shared__ __align__(16) float Bs[16][128];
    const int tid = threadIdx.x;
    const int row_t = tid >> 3;        // 0..15 -> 8 rows each
    const int col_t = tid & 7;         // 0..7  -> 16 cols each
    const int m0 = blockIdx.x * 128;
    const int arow = m0 + tid;         // A-load row (one per thread)

    unsigned long long acc[4][16];     // 4 row-pairs x 16 cols, packed f32x2
#pragma unroll
    for (int p = 0; p < 4; p++)
#pragma unroll
        for (int j = 0; j < 16; j++) acc[p][j] = 0ull;

    const int b_k = tid >> 3;          // 0..15: B row within tile
    const int b_j = (tid & 7) * 16;    // 16 floats

    for (int k0 = 0; k0 < K; k0 += 16) {
        // ---- A tile load (+ optional norm_d scale) ----
        float4 av[4];
        if (arow < M) {
            const float* ap;
            float nd = 1.f;
            if (LAYER) {
                int r = k0 >> 7;                       // constant across BK=16
                ap = g_agg + ((size_t)r * NN + arow) * 128 + (k0 & 127);
                nd = __ldg(&g_norm_d[r * NN + arow]);
            } else {
                ap = A + (size_t)arow * K + k0;
            }
#pragma unroll
            for (int q = 0; q < 4; q++) {
                av[q] = *(const float4*)(ap + q * 4);
                if (LAYER) {
                    av[q].x *= nd; av[q].y *= nd; av[q].z *= nd; av[q].w *= nd;
                }
            }
        } else {
#pragma unroll
            for (int q = 0; q < 4; q++) av[q] = make_float4(0.f, 0.f, 0.f, 0.f);
        }
#pragma unroll
        for (int q = 0; q < 4; q++) {
            As[q * 4 + 0][tid] = av[q].x;
            As[q * 4 + 1][tid] = av[q].y;
            As[q * 4 + 2][tid] = av[q].z;
            As[q * 4 + 3][tid] = av[q].w;
        }
        // ---- B tile load ----
        {
            const float* bp = B + (size_t)(k0 + b_k) * HID + b_j;
#pragma unroll
            for (int q = 0; q < 4; q++)
                *(float4*)&Bs[b_k][b_j + q * 4] = *(const float4*)(bp + q * 4);
        }
        __syncthreads();

#pragma unroll
        for (int k = 0; k < 16; k++) {
            ulonglong2 A0 = *(const ulonglong2*)&As[k][row_t * 8];
            ulonglong2 A1 = *(const ulonglong2*)&As[k][row_t * 8 + 4];
            unsigned long long ap2[4] = {A0.x, A0.y, A1.x, A1.y};
            float4 b0 = *(const float4*)&Bs[k][col_t * 16];
            float4 b1 = *(const float4*)&Bs[k][col_t * 16 + 4];
            float4 b2 = *(const float4*)&Bs[k][col_t * 16 + 8];
            float4 b3 = *(const float4*)&Bs[k][col_t * 16 + 12];
            float bf[16] = {b0.x, b0.y, b0.z, b0.w, b1.x, b1.y, b1.z, b1.w,
                            b2.x, b2.y, b2.z, b2.w, b3.x, b3.y, b3.z, b3.w};
            unsigned long long bp2[16];
#pragma unroll
            for (int j = 0; j < 16; j++) bp2[j] = pack_dup(bf[j]);
#pragma unroll
            for (int p = 0; p < 4; p++)
#pragma unroll
                for (int j = 0; j < 16; j++) ffma2(acc[p][j], ap2[p], bp2[j]);
        }
        __syncthreads();
    }

    // ---- epilogue ----
    float bcol[16];
#pragma unroll
    for (int j = 0; j < 16; j++) {
        int c = col_t * 16 + j;
        if (LAYER) {
            float s = 0.f;
#pragma unroll
            for (int r = 0; r < RR; r++) s += __ldg(&bias[r * HID + c]);
            bcol[j] = s;
        } else {
            bcol[j] = __ldg(&bias[c]);
        }
    }
#pragma unroll
    for (int p = 0; p < 4; p++) {
        int r0 = m0 + row_t * 8 + p * 2;
        float lo[16], hi[16];
#pragma unroll
        for (int j = 0; j < 16; j++) {
            unpack2(acc[p][j], lo[j], hi[j]);
            lo[j] += bcol[j]; hi[j] += bcol[j];
            if (RELU) { lo[j] = fmaxf(lo[j], 0.f); hi[j] = fmaxf(hi[j], 0.f); }
        }
        if (r0 < M) {
            float* cr = C + (size_t)r0 * HID + col_t * 16;
#pragma unroll
            for (int q = 0; q < 4; q++)
                *(float4*)(cr + q * 4) = make_float4(lo[q*4], lo[q*4+1], lo[q*4+2], lo[q*4+3]);
        }
        if (r0 + 1 < M) {
            float* cr = C + (size_t)(r0 + 1) * HID + col_t * 16;
#pragma unroll
            for (int q = 0; q < 4; q++)
                *(float4*)(cr + q * 4) = make_float4(hi[q*4], hi[q*4+1], hi[q*4+2], hi[q*4+3]);
        }
    }
}

// ---------------- ragged masked mean: one warp per row ----------------
__global__ void k_rowmean(const float* __restrict__ h, const int* __restrict__ ridx,
                          const unsigned char* __restrict__ rmask, float* __restrict__ outm) {
    long long gtid = (long long)blockIdx.x * blockDim.x + threadIdx.x;
    long long w = gtid >> 5;
    if (w >= NR) return;
    int lane = threadIdx.x & 31;
    const int is_int = g_mask_is_int;
    const int* rmask_i = (const int*)rmask;
    float4 acc = make_float4(0.f, 0.f, 0.f, 0.f);
    float cnt = 0.f;
#pragma unroll
    for (int f = 0; f < FF; f++) {
        bool on = is_int ? (__ldg(&rmask_i[w * FF + f]) != 0) : (rmask[w * FF + f] != 0);
        if (on) {
            int idx = __ldg(&ridx[w * FF + f]);
            float4 v = __ldg((const float4*)(h + (size_t)idx * HID) + lane);
            acc.x += v.x; acc.y += v.y; acc.z += v.z; acc.w += v.w;
            cnt += 1.f;
        }
    }
    float inv = 1.f / fmaxf(cnt, 1.f);
    acc.x *= inv; acc.y *= inv; acc.z *= inv; acc.w *= inv;
    *((float4*)(outm + (size_t)w * HID) + lane) = acc;
}

// ---------------- final head: [NR][128] @ [128][10] + b ----------------
__global__ void k_head(const float* __restrict__ X, const float* __restrict__ W,
                       const float* __restrict__ b, float* __restrict__ out) {
    long long t = (long long)blockIdx.x * blockDim.x + threadIdx.x;
    int row = (int)(t >> 4);
    int c = (int)(t & 15);
    if (row >= NR || c >= NC) return;
    const float* x = X + (size_t)row * HID;
    float acc = b[c];
#pragma unroll
    for (int k = 0; k < HID; k++) acc += x[k] * __ldg(&W[k * NC + c]);
    out[(size_t)row * NC + c] = acc;
}

// ---------------- launch ----------------
extern "C" void kernel_launch(void* const* d_in, const int* in_sizes, int n_in,
                              void* d_out, int out_size) {
    const float* node_feats = (const float*)d_in[0];
    const int*   edges_src  = (const int*)  d_in[1];
    const int*   edges_dst  = (const int*)  d_in[2];
    const int*   row_idx    = (const int*)  d_in[3];
    const unsigned char* row_mask = (const unsigned char*)d_in[4];
    const float* W_in = (const float*)d_in[5];
    const float* b_in = (const float*)d_in[6];
    const float* W1   = (const float*)d_in[7];
    const float* b1   = (const float*)d_in[8];
    const float* W2   = (const float*)d_in[9];
    const float* b2   = (const float*)d_in[10];
    const float* Wm1  = (const float*)d_in[11];
    const float* bm1  = (const float*)d_in[12];
    const float* Wm2  = (const float*)d_in[13];
    const float* bm2  = (const float*)d_in[14];
    const float* Wm3  = (const float*)d_in[15];
    const float* bm3  = (const float*)d_in[16];
    float* out = (float*)d_out;

    float *p_h0, *p_h1, *p_h2, *p_agg, *p_dego, *p_degi, *p_mean, *p_x1, *p_x2;
    cudaGetSymbolAddress((void**)&p_h0,   g_h0);
    cudaGetSymbolAddress((void**)&p_h1,   g_h1);
    cudaGetSymbolAddress((void**)&p_h2,   g_h2);
    cudaGetSymbolAddress((void**)&p_agg,  g_agg);
    cudaGetSymbolAddress((void**)&p_dego, g_deg_out);
    cudaGetSymbolAddress((void**)&p_degi, g_deg_in);
    cudaGetSymbolAddress((void**)&p_mean, g_mean);
    cudaGetSymbolAddress((void**)&p_x1,   g_x1);
    cudaGetSymbolAddress((void**)&p_x2,   g_x2);

    const long long agg4 = (long long)RR * NN * HID / 4;
    const long long deg4 = (long long)RR * NN / 4;
    const int gb_nn = (NN + 127) / 128;   // 297
    const int gb_nr = (NR + 127) / 128;   // 469

    // mask dtype detection
    k_detect_mask<<<1, 256>>>(row_mask);

    // degrees + norms
    k_zero4<<<2048, 256>>>((float4*)p_dego, deg4);
    k_zero4<<<2048, 256>>>((float4*)p_degi, deg4);
    k_deg<<<(RR * EE + 255) / 256, 256>>>(edges_src, edges_dst);
    k_norms<<<(RR * NN + 255) / 256, 256>>>();

    // input linear + relu
    k_fgemm<true, false><<<gb_nn, 128>>>(node_feats, W_in, b_in, p_h0, NN, IND);

    // RGCN layer 1
    k_zero4<<<8192, 256>>>((float4*)p_agg, agg4);
    {
        long long nt = (long long)RR * EE * 32;
        k_agg<<<(unsigned)((nt + 255) / 256), 256>>>(p_h0, edges_src, edges_dst);
    }
    k_fgemm<true, true><<<gb_nn, 128>>>(nullptr, W1, b1, p_h1, NN, RR * HID);

    // RGCN layer 2
    k_zero4<<<8192, 256>>>((float4*)p_agg, agg4);
    {
        long long nt = (long long)RR * EE * 32;
        k_agg<<<(unsigned)((nt + 255) / 256), 256>>>(p_h1, edges_src, edges_dst);
    }
    k_fgemm<false, true><<<gb_nn, 128>>>(nullptr, W2, b2, p_h2, NN, RR * HID);

    // ragged masked mean
    {
        long long nt = (long long)NR * 32;
        k_rowmean<<<(unsigned)((nt + 255) / 256), 256>>>(p_h2, row_idx, row_mask, p_mean);
    }

    // MLP head
    k_fgemm<true, false><<<gb_nr, 128>>>(p_mean, Wm1, bm1, p_x1, NR, HID);
    k_fgemm<true, false><<<gb_nr, 128>>>(p_x1,  Wm2, bm2, p_x2, NR, HID);
    k_head<<<(NR * 16 + 255) / 256, 256>>>(p_x2, Wm3, bm3, out);

    (void)in_sizes; (void)n_in; (void)out_size;
}

// round 10
// speedup vs baseline: 1.6943x; 1.6943x over previous
#include <cuda_runtime.h>
#include <cuda_bf16.h>
#include <cstdint>

// ---------------- problem constants ----------------
constexpr int NN  = 38000;   // nodes
constexpr int IND = 64;      // input dim
constexpr int HID = 128;
constexpr int RR  = 8;       // relations
constexpr int EE  = 200000;  // edges per relation
constexpr int NR  = 60000;   // rows
constexpr int FF  = 19;      // features per row
constexpr int NC  = 10;      // classes

// ---------------- device scratch (static, no allocation) ----------------
__device__ float g_h0[(size_t)NN * HID];
__device__ float g_h1[(size_t)NN * HID];
__device__ float g_h2[(size_t)NN * HID];
__device__ float g_agg[(size_t)RR * NN * HID];      // 155.6 MB
__device__ float g_deg_out[RR * NN];
__device__ float g_deg_in[RR * NN];
__device__ float g_norm_s[RR * NN];
__device__ float g_norm_d[RR * NN];
__device__ float g_mean[(size_t)NR * HID];
__device__ float g_x1[(size_t)NR * HID];
__device__ float g_x2[(size_t)NR * HID];
__device__ int   g_mask_is_int;

// ---------------- helpers ----------------
__device__ __forceinline__ uint32_t smem_u32(const void* p) {
    uint32_t a;
    asm("{ .reg .u64 t; cvta.to.shared.u64 t, %1; cvt.u32.u64 %0, t; }" : "=r"(a) : "l"(p));
    return a;
}

// convert 8 fp32 -> packed bf16 hi (uint4) + residual lo (uint4)
__device__ __forceinline__ void cvt8(const float* f, uint4& hi, uint4& lo) {
    unsigned h[4], l[4];
#pragma unroll
    for (int i = 0; i < 4; i++) {
        float f0 = f[2 * i], f1 = f[2 * i + 1];
        __nv_bfloat16 b0 = __float2bfloat16(f0), b1 = __float2bfloat16(f1);
        __nv_bfloat16 c0 = __float2bfloat16(f0 - __bfloat162float(b0));
        __nv_bfloat16 c1 = __float2bfloat16(f1 - __bfloat162float(b1));
        h[i] = (unsigned)__bfloat16_as_ushort(b0) | ((unsigned)__bfloat16_as_ushort(b1) << 16);
        l[i] = (unsigned)__bfloat16_as_ushort(c0) | ((unsigned)__bfloat16_as_ushort(c1) << 16);
    }
    hi = make_uint4(h[0], h[1], h[2], h[3]);
    lo = make_uint4(l[0], l[1], l[2], l[3]);
}

__device__ __forceinline__ void ldsm_x4(uint32_t* r, uint32_t addr) {
    asm volatile("ldmatrix.sync.aligned.m8n8.x4.shared.b16 {%0,%1,%2,%3}, [%4];"
                 : "=r"(r[0]), "=r"(r[1]), "=r"(r[2]), "=r"(r[3]) : "r"(addr));
}
__device__ __forceinline__ void ldsm_x4_t(uint32_t* r, uint32_t addr) {
    asm volatile("ldmatrix.sync.aligned.m8n8.x4.trans.shared.b16 {%0,%1,%2,%3}, [%4];"
                 : "=r"(r[0]), "=r"(r[1]), "=r"(r[2]), "=r"(r[3]) : "r"(addr));
}
__device__ __forceinline__ void mma_bf16(float* c, const uint32_t* a, const uint32_t* b) {
    asm volatile("mma.sync.aligned.m16n8k16.row.col.f32.bf16.bf16.f32 "
                 "{%0,%1,%2,%3}, {%4,%5,%6,%7}, {%8,%9}, {%0,%1,%2,%3};"
                 : "+f"(c[0]), "+f"(c[1]), "+f"(c[2]), "+f"(c[3])
                 : "r"(a[0]), "r"(a[1]), "r"(a[2]), "r"(a[3]), "r"(b[0]), "r"(b[1]));
}

// ---------------- zero ----------------
__global__ void k_zero4(float4* p, long long n4) {
    long long i = (long long)blockIdx.x * blockDim.x + threadIdx.x;
    long long stride = (long long)gridDim.x * blockDim.x;
    float4 z = make_float4(0.f, 0.f, 0.f, 0.f);
    for (; i < n4; i += stride) p[i] = z;
}

// ---------------- mask dtype detection (bool stored as u8 vs i32) ----------
__global__ void k_detect_mask(const unsigned char* __restrict__ m) {
    __shared__ int cnt;
    if (threadIdx.x == 0) cnt = 0;
    __syncthreads();
    int local = 0;
    for (int i = threadIdx.x; i < 65536; i += blockDim.x) local += (m[i] != 0);
    atomicAdd(&cnt, local);
    __syncthreads();
    if (threadIdx.x == 0) g_mask_is_int = (cnt < 16384) ? 1 : 0;
}

// ---------------- degrees + norms ----------------
__global__ void k_deg(const int* __restrict__ src, const int* __restrict__ dst) {
    long long i = (long long)blockIdx.x * blockDim.x + threadIdx.x;
    if (i >= (long long)RR * EE) return;
    int r = (int)(i / EE);
    atomicAdd(&g_deg_out[r * NN + src[i]], 1.f);
    atomicAdd(&g_deg_in [r * NN + dst[i]], 1.f);
}
__global__ void k_norms() {
    int i = blockIdx.x * blockDim.x + threadIdx.x;
    if (i >= RR * NN) return;
    g_norm_s[i] = rsqrtf(fmaxf(g_deg_out[i], 1.f));
    g_norm_d[i] = rsqrtf(fmaxf(g_deg_in [i], 1.f));
}

// ---------------- edge aggregation: one warp per edge, float4 RED ----------------
__global__ void k_agg(const float* __restrict__ h,
                      const int* __restrict__ src, const int* __restrict__ dst) {
    long long gtid = (long long)blockIdx.x * blockDim.x + threadIdx.x;
    long long w = gtid >> 5;
    if (w >= (long long)RR * EE) return;
    int lane = threadIdx.x & 31;
    int r = (int)(w / EE);
    int s = __ldg(&src[w]);
    int d = __ldg(&dst[w]);
    float sc = __ldg(&g_norm_s[(size_t)r * NN + s]);
    float4 v = __ldg((const float4*)(h + (size_t)s * HID) + lane);
    v.x *= sc; v.y *= sc; v.z *= sc; v.w *= sc;
    atomicAdd((float4*)(g_agg + ((size_t)r * NN + d) * HID) + lane, v);
}

// ---------------- tensor-core split-bf16 GEMM ----------------
// C[M][128] = epi(A'[M][K] @ B[K][128] + bias); fp32 in/out, internally
// split bf16 (hi+lo, 3 mma passes) with fp32 accumulation.
// BM=128, BN=128, BK=16, 256 threads (8 warps: 2x4), 4x4 m16n8k16 tiles/warp.
// LAYER: A' = implicit [NN][R*128] from g_agg scaled by norm_d[r][row];
//        bias = sum_r bias[r][:].
template <bool RELU, bool LAYER>
__global__ __launch_bounds__(256, 2)
void k_tmma(const float* __restrict__ A, const float* __restrict__ B,
            const float* __restrict__ bias, float* __restrict__ C,
            int M, int K) {
    __shared__ __align__(16) unsigned char sAhi[4096];   // 128 x 16 bf16, 32B rows
    __shared__ __align__(16) unsigned char sAlo[4096];
    __shared__ __align__(16) unsigned char sBhi[8192];   // 16 x 128 bf16, 256B rows
    __shared__ __align__(16) unsigned char sBlo[8192];

    const int tid = threadIdx.x;
    const int wid = tid >> 5, lane = tid & 31;
    const int warp_m = wid & 1;        // 2 x 64 rows
    const int warp_n = wid >> 1;       // 4 x 32 cols
    const int m0 = blockIdx.x * 128;

    float acc[4][4][4];
#pragma unroll
    for (int mt = 0; mt < 4; mt++)
#pragma unroll
        for (int nt = 0; nt < 4; nt++)
#pragma unroll
            for (int q = 0; q < 4; q++) acc[mt][nt][q] = 0.f;

    // loader indices
    const int a_row  = tid >> 1;          // 0..127
    const int a_half = tid & 1;           // 8 floats each
    const int arow_g = m0 + a_row;
    const int b_kr   = tid >> 4;          // 0..15
    const int b_n0   = (tid & 15) * 8;

    const uint32_t uAhi = smem_u32(sAhi), uAlo = smem_u32(sAlo);
    const uint32_t uBhi = smem_u32(sBhi), uBlo = smem_u32(sBlo);

    // per-lane ldmatrix addresses (constant over k-steps)
    uint32_t a_addr[4], b_addr[2];
#pragma unroll
    for (int mt = 0; mt < 4; mt++) {
        int row = warp_m * 64 + mt * 16 + (lane & 15);
        uint32_t byte = (uint32_t)row * 32 + (uint32_t)(lane >> 4) * 16;
        byte ^= ((uint32_t)(row >> 2) & 1u) << 4;
        a_addr[mt] = byte;
    }
#pragma unroll
    for (int p = 0; p < 2; p++) {
        int kk = lane & 15;
        int ncol = warp_n * 32 + p * 16 + ((lane >> 4) << 3);
        uint32_t byte = (uint32_t)kk * 256 + (uint32_t)ncol * 2;
        byte ^= ((uint32_t)kk & 7u) << 4;
        b_addr[p] = byte;
    }

    // A-tile smem store address (constant)
    uint32_t sa_byte = (uint32_t)a_row * 32 + (uint32_t)a_half * 16;
    sa_byte ^= ((uint32_t)(a_row >> 2) & 1u) << 4;
    // B-tile smem store address (constant)
    uint32_t sb_byte = (uint32_t)b_kr * 256 + (uint32_t)b_n0 * 2;
    sb_byte ^= ((uint32_t)b_kr & 7u) << 4;

    for (int k0 = 0; k0 < K; k0 += 16) {
        // ---- stage A tile (fp32 -> bf16 hi/lo) ----
        {
            float f[8];
            if (arow_g < M) {
                const float* ap;
                float nd = 1.f;
                if (LAYER) {
                    int r = k0 >> 7;               // constant within tile
                    ap = g_agg + ((size_t)r * NN + arow_g) * 128 + (k0 & 127) + a_half * 8;
                    nd = __ldg(&g_norm_d[r * NN + arow_g]);
                } else {
                    ap = A + (size_t)arow_g * K + k0 + a_half * 8;
                }
                float4 v0 = *(const float4*)ap;
                float4 v1 = *(const float4*)(ap + 4);
                f[0] = v0.x; f[1] = v0.y; f[2] = v0.z; f[3] = v0.w;
                f[4] = v1.x; f[5] = v1.y; f[6] = v1.z; f[7] = v1.w;
                if (LAYER) {
#pragma unroll
                    for (int i = 0; i < 8; i++) f[i] *= nd;
                }
            } else {
#pragma unroll
                for (int i = 0; i < 8; i++) f[i] = 0.f;
            }
            uint4 hi, lo;
            cvt8(f, hi, lo);
            *(uint4*)(sAhi + sa_byte) = hi;
            *(uint4*)(sAlo + sa_byte) = lo;
        }
        // ---- stage B tile ----
        {
            const float* bp = B + (size_t)(k0 + b_kr) * HID + b_n0;
            float f[8];
            float4 v0 = *(const float4*)bp;
            float4 v1 = *(const float4*)(bp + 4);
            f[0] = v0.x; f[1] = v0.y; f[2] = v0.z; f[3] = v0.w;
            f[4] = v1.x; f[5] = v1.y; f[6] = v1.z; f[7] = v1.w;
            uint4 hi, lo;
            cvt8(f, hi, lo);
            *(uint4*)(sBhi + sb_byte) = hi;
            *(uint4*)(sBlo + sb_byte) = lo;
        }
        __syncthreads();

        // ---- fragments ----
        uint32_t ah[4][4], al[4][4], bh[2][4], bl[2][4];
#pragma unroll
        for (int mt = 0; mt < 4; mt++) {
            ldsm_x4(ah[mt], uAhi + a_addr[mt]);
            ldsm_x4(al[mt], uAlo + a_addr[mt]);
        }
#pragma unroll
        for (int p = 0; p < 2; p++) {
            ldsm_x4_t(bh[p], uBhi + b_addr[p]);
            ldsm_x4_t(bl[p], uBlo + b_addr[p]);
        }
        // ---- mma: hi*hi + hi*lo + lo*hi ----
#pragma unroll
        for (int mt = 0; mt < 4; mt++) {
#pragma unroll
            for (int nt = 0; nt < 4; nt++) {
                const int p = nt >> 1, w = (nt & 1) * 2;
                uint32_t bhx[2] = {bh[p][w], bh[p][w + 1]};
                uint32_t blx[2] = {bl[p][w], bl[p][w + 1]};
                mma_bf16(acc[mt][nt], ah[mt], bhx);
                mma_bf16(acc[mt][nt], ah[mt], blx);
                mma_bf16(acc[mt][nt], al[mt], bhx);
            }
        }
        __syncthreads();
    }

    // ---- epilogue ----
#pragma unroll
    for (int nt = 0; nt < 4; nt++) {
        int cc = warp_n * 32 + nt * 8 + (lane & 3) * 2;
        float b0, b1;
        if (LAYER) {
            float s0 = 0.f, s1 = 0.f;
#pragma unroll
            for (int r = 0; r < RR; r++) {
                s0 += __ldg(&bias[r * HID + cc]);
                s1 += __ldg(&bias[r * HID + cc + 1]);
            }
            b0 = s0; b1 = s1;
        } else {
            b0 = __ldg(&bias[cc]); b1 = __ldg(&bias[cc + 1]);
        }
#pragma unroll
        for (int mt = 0; mt < 4; mt++) {
            int rg = m0 + warp_m * 64 + mt * 16 + (lane >> 2);
            float o0 = acc[mt][nt][0] + b0, o1 = acc[mt][nt][1] + b1;
            float o2 = acc[mt][nt][2] + b0, o3 = acc[mt][nt][3] + b1;
            if (RELU) {
                o0 = fmaxf(o0, 0.f); o1 = fmaxf(o1, 0.f);
                o2 = fmaxf(o2, 0.f); o3 = fmaxf(o3, 0.f);
            }
            if (rg < M)     *(float2*)(C + (size_t)rg * HID + cc)       = make_float2(o0, o1);
            if (rg + 8 < M) *(float2*)(C + (size_t)(rg + 8) * HID + cc) = make_float2(o2, o3);
        }
    }
}

// ---------------- ragged masked mean: one warp per row ----------------
__global__ void k_rowmean(const float* __restrict__ h, const int* __restrict__ ridx,
                          const unsigned char* __restrict__ rmask, float* __restrict__ outm) {
    long long gtid = (long long)blockIdx.x * blockDim.x + threadIdx.x;
    long long w = gtid >> 5;
    if (w >= NR) return;
    int lane = threadIdx.x & 31;
    const int is_int = g_mask_is_int;
    const int* rmask_i = (const int*)rmask;
    float4 acc = make_float4(0.f, 0.f, 0.f, 0.f);
    float cnt = 0.f;
#pragma unroll
    for (int f = 0; f < FF; f++) {
        bool on = is_int ? (__ldg(&rmask_i[w * FF + f]) != 0) : (rmask[w * FF + f] != 0);
        if (on) {
            int idx = __ldg(&ridx[w * FF + f]);
            float4 v = __ldg((const float4*)(h + (size_t)idx * HID) + lane);
            acc.x += v.x; acc.y += v.y; acc.z += v.z; acc.w += v.w;
            cnt += 1.f;
        }
    }
    float inv = 1.f / fmaxf(cnt, 1.f);
    acc.x *= inv; acc.y *= inv; acc.z *= inv; acc.w *= inv;
    *((float4*)(outm + (size_t)w * HID) + lane) = acc;
}

// ---------------- final head: [NR][128] @ [128][10] + b (fp32) ----------------
__global__ void k_head(const float* __restrict__ X, const float* __restrict__ W,
                       const float* __restrict__ b, float* __restrict__ out) {
    long long t = (long long)blockIdx.x * blockDim.x + threadIdx.x;
    int row = (int)(t >> 4);
    int c = (int)(t & 15);
    if (row >= NR || c >= NC) return;
    const float* x = X + (size_t)row * HID;
    float acc = b[c];
#pragma unroll
    for (int k = 0; k < HID; k++) acc += x[k] * __ldg(&W[k * NC + c]);
    out[(size_t)row * NC + c] = acc;
}

// ---------------- launch ----------------
extern "C" void kernel_launch(void* const* d_in, const int* in_sizes, int n_in,
                              void* d_out, int out_size) {
    const float* node_feats = (const float*)d_in[0];
    const int*   edges_src  = (const int*)  d_in[1];
    const int*   edges_dst  = (const int*)  d_in[2];
    const int*   row_idx    = (const int*)  d_in[3];
    const unsigned char* row_mask = (const unsigned char*)d_in[4];
    const float* W_in = (const float*)d_in[5];
    const float* b_in = (const float*)d_in[6];
    const float* W1   = (const float*)d_in[7];
    const float* b1   = (const float*)d_in[8];
    const float* W2   = (const float*)d_in[9];
    const float* b2   = (const float*)d_in[10];
    const float* Wm1  = (const float*)d_in[11];
    const float* bm1  = (const float*)d_in[12];
    const float* Wm2  = (const float*)d_in[13];
    const float* bm2  = (const float*)d_in[14];
    const float* Wm3  = (const float*)d_in[15];
    const float* bm3  = (const float*)d_in[16];
    float* out = (float*)d_out;

    float *p_h0, *p_h1, *p_h2, *p_agg, *p_dego, *p_degi, *p_mean, *p_x1, *p_x2;
    cudaGetSymbolAddress((void**)&p_h0,   g_h0);
    cudaGetSymbolAddress((void**)&p_h1,   g_h1);
    cudaGetSymbolAddress((void**)&p_h2,   g_h2);
    cudaGetSymbolAddress((void**)&p_agg,  g_agg);
    cudaGetSymbolAddress((void**)&p_dego, g_deg_out);
    cudaGetSymbolAddress((void**)&p_degi, g_deg_in);
    cudaGetSymbolAddress((void**)&p_mean, g_mean);
    cudaGetSymbolAddress((void**)&p_x1,   g_x1);
    cudaGetSymbolAddress((void**)&p_x2,   g_x2);

    const long long agg4 = (long long)RR * NN * HID / 4;
    const long long deg4 = (long long)RR * NN / 4;
    const int gb_nn = (NN + 127) / 128;   // 297
    const int gb_nr = (NR + 127) / 128;   // 469

    // mask dtype detection
    k_detect_mask<<<1, 256>>>(row_mask);

    // degrees + norms
    k_zero4<<<2048, 256>>>((float4*)p_dego, deg4);
    k_zero4<<<2048, 256>>>((float4*)p_degi, deg4);
    k_deg<<<(RR * EE + 255) / 256, 256>>>(edges_src, edges_dst);
    k_norms<<<(RR * NN + 255) / 256, 256>>>();

    // input linear + relu
    k_tmma<true, false><<<gb_nn, 256>>>(node_feats, W_in, b_in, p_h0, NN, IND);

    // RGCN layer 1
    k_zero4<<<8192, 256>>>((float4*)p_agg, agg4);
    {
        long long nt = (long long)RR * EE * 32;
        k_agg<<<(unsigned)((nt + 255) / 256), 256>>>(p_h0, edges_src, edges_dst);
    }
    k_tmma<true, true><<<gb_nn, 256>>>(nullptr, W1, b1, p_h1, NN, RR * HID);

    // RGCN layer 2
    k_zero4<<<8192, 256>>>((float4*)p_agg, agg4);
    {
        long long nt = (long long)RR * EE * 32;
        k_agg<<<(unsigned)((nt + 255) / 256), 256>>>(p_h1, edges_src, edges_dst);
    }
    k_tmma<false, true><<<gb_nn, 256>>>(nullptr, W2, b2, p_h2, NN, RR * HID);

    // ragged masked mean
    {
        long long nt = (long long)NR * 32;
        k_rowmean<<<(unsigned)((nt + 255) / 256), 256>>>(p_h2, row_idx, row_mask, p_mean);
    }

    // MLP head
    k_tmma<true, false><<<gb_nr, 256>>>(p_mean, Wm1, bm1, p_x1, NR, HID);
    k_tmma<true, false><<<gb_nr, 256>>>(p_x1,  Wm2, bm2, p_x2, NR, HID);
    k_head<<<(NR * 16 + 255) / 256, 256>>>(p_x2, Wm3, bm3, out);

    (void)in_sizes; (void)n_in; (void)out_size;
}

// round 11
// speedup vs baseline: 1.7424x; 1.0284x over previous
#include <cuda_runtime.h>
#include <cuda_bf16.h>
#include <cstdint>

// ---------------- problem constants ----------------
constexpr int NN  = 38000;   // nodes
constexpr int IND = 64;      // input dim
constexpr int HID = 128;
constexpr int RR  = 8;       // relations
constexpr int EE  = 200000;  // edges per relation
constexpr int NR  = 60000;   // rows
constexpr int FF  = 19;      // features per row
constexpr int NC  = 10;      // classes

// ---------------- device scratch (static, no allocation) ----------------
__device__ float g_h0[(size_t)NN * HID];     // relu(X @ W_in + b_in)
__device__ float g_acc1[(size_t)NN * HID];   // layer-1 accumulator (pre-relu)
__device__ float g_acc2[(size_t)NN * HID];   // layer-2 accumulator (= h2)
__device__ float g_z[(size_t)NN * HID];      // per-relation transformed feats
__device__ float g_deg_out[RR * NN];
__device__ float g_deg_in[RR * NN];
__device__ float g_norm_s[RR * NN];
__device__ float g_norm_d[RR * NN];
__device__ float g_mean[(size_t)NR * HID];
__device__ float g_x1[(size_t)NR * HID];
__device__ float g_x2[(size_t)NR * HID];
__device__ int   g_mask_is_int;

// ---------------- helpers ----------------
__device__ __forceinline__ uint32_t smem_u32(const void* p) {
    uint32_t a;
    asm("{ .reg .u64 t; cvta.to.shared.u64 t, %1; cvt.u32.u64 %0, t; }" : "=r"(a) : "l"(p));
    return a;
}

// convert 8 fp32 -> packed bf16 hi (uint4) + residual lo (uint4)
__device__ __forceinline__ void cvt8(const float* f, uint4& hi, uint4& lo) {
    unsigned h[4], l[4];
#pragma unroll
    for (int i = 0; i < 4; i++) {
        float f0 = f[2 * i], f1 = f[2 * i + 1];
        __nv_bfloat16 b0 = __float2bfloat16(f0), b1 = __float2bfloat16(f1);
        __nv_bfloat16 c0 = __float2bfloat16(f0 - __bfloat162float(b0));
        __nv_bfloat16 c1 = __float2bfloat16(f1 - __bfloat162float(b1));
        h[i] = (unsigned)__bfloat16_as_ushort(b0) | ((unsigned)__bfloat16_as_ushort(b1) << 16);
        l[i] = (unsigned)__bfloat16_as_ushort(c0) | ((unsigned)__bfloat16_as_ushort(c1) << 16);
    }
    hi = make_uint4(h[0], h[1], h[2], h[3]);
    lo = make_uint4(l[0], l[1], l[2], l[3]);
}

__device__ __forceinline__ void ldsm_x4(uint32_t* r, uint32_t addr) {
    asm volatile("ldmatrix.sync.aligned.m8n8.x4.shared.b16 {%0,%1,%2,%3}, [%4];"
                 : "=r"(r[0]), "=r"(r[1]), "=r"(r[2]), "=r"(r[3]) : "r"(addr));
}
__device__ __forceinline__ void ldsm_x4_t(uint32_t* r, uint32_t addr) {
    asm volatile("ldmatrix.sync.aligned.m8n8.x4.trans.shared.b16 {%0,%1,%2,%3}, [%4];"
                 : "=r"(r[0]), "=r"(r[1]), "=r"(r[2]), "=r"(r[3]) : "r"(addr));
}
__device__ __forceinline__ void mma_bf16(float* c, const uint32_t* a, const uint32_t* b) {
    asm volatile("mma.sync.aligned.m16n8k16.row.col.f32.bf16.bf16.f32 "
                 "{%0,%1,%2,%3}, {%4,%5,%6,%7}, {%8,%9}, {%0,%1,%2,%3};"
                 : "+f"(c[0]), "+f"(c[1]), "+f"(c[2]), "+f"(c[3])
                 : "r"(a[0]), "r"(a[1]), "r"(a[2]), "r"(a[3]), "r"(b[0]), "r"(b[1]));
}

// ---------------- zero ----------------
__global__ void k_zero4(float4* p, long long n4) {
    long long i = (long long)blockIdx.x * blockDim.x + threadIdx.x;
    long long stride = (long long)gridDim.x * blockDim.x;
    float4 z = make_float4(0.f, 0.f, 0.f, 0.f);
    for (; i < n4; i += stride) p[i] = z;
}

// ---------------- mask dtype detection (bool stored as u8 vs i32) ----------
__global__ void k_detect_mask(const unsigned char* __restrict__ m) {
    __shared__ int cnt;
    if (threadIdx.x == 0) cnt = 0;
    __syncthreads();
    int local = 0;
    for (int i = threadIdx.x; i < 65536; i += blockDim.x) local += (m[i] != 0);
    atomicAdd(&cnt, local);
    __syncthreads();
    if (threadIdx.x == 0) g_mask_is_int = (cnt < 16384) ? 1 : 0;
}

// ---------------- degrees + norms ----------------
__global__ void k_deg(const int* __restrict__ src, const int* __restrict__ dst) {
    long long i = (long long)blockIdx.x * blockDim.x + threadIdx.x;
    if (i >= (long long)RR * EE) return;
    int r = (int)(i / EE);
    atomicAdd(&g_deg_out[r * NN + src[i]], 1.f);
    atomicAdd(&g_deg_in [r * NN + dst[i]], 1.f);
}
__global__ void k_norms() {
    int i = blockIdx.x * blockDim.x + threadIdx.x;
    if (i >= RR * NN) return;
    g_norm_s[i] = rsqrtf(fmaxf(g_deg_out[i], 1.f));
    g_norm_d[i] = rsqrtf(fmaxf(g_deg_in [i], 1.f));
}

// ---------------- accumulator init: acc[n][c] = sum_r b[r][c] ----------------
__global__ void k_bias_init(const float* __restrict__ b, float* __restrict__ acc) {
    long long i = (long long)blockIdx.x * blockDim.x + threadIdx.x;
    if (i >= (long long)NN * HID) return;
    int c = (int)(i & (HID - 1));
    float s = 0.f;
#pragma unroll
    for (int r = 0; r < RR; r++) s += __ldg(&b[r * HID + c]);
    acc[i] = s;
}

// ---------------- per-relation edge scatter: acc[dst] += z[src]*ns[src]*nd[dst] ---
__global__ void k_agg3(const float* __restrict__ z,
                       const int* __restrict__ src, const int* __restrict__ dst,
                       const float* __restrict__ ns_r, const float* __restrict__ nd_r,
                       float* __restrict__ acc) {
    long long gtid = (long long)blockIdx.x * blockDim.x + threadIdx.x;
    long long w = gtid >> 5;
    if (w >= EE) return;
    int lane = threadIdx.x & 31;
    int sidx = __ldg(&src[w]);
    int didx = __ldg(&dst[w]);
    float sc = __ldg(&ns_r[sidx]) * __ldg(&nd_r[didx]);
    float4 v = __ldg((const float4*)(z + (size_t)sidx * HID) + lane);
    v.x *= sc; v.y *= sc; v.z *= sc; v.w *= sc;
    atomicAdd((float4*)(acc + (size_t)didx * HID) + lane, v);
}

// ---------------- tensor-core split-bf16 GEMM ----------------
// C[M][128] = epi(pre(A)[M][K] @ B[K][128] [+ bias]); fp32 in/out, internally
// split bf16 (hi+lo, 3 mma passes) with fp32 accumulation.
// BM=128, BN=128, BK=16, 256 threads (8 warps: 2x4), 4x4 m16n8k16 tiles/warp.
template <bool RELU_EPI, bool RELU_IN, bool BIAS>
__global__ __launch_bounds__(256, 2)
void k_tmma(const float* __restrict__ A, const float* __restrict__ B,
            const float* __restrict__ bias, float* __restrict__ C,
            int M, int K) {
    __shared__ __align__(16) unsigned char sAhi[4096];   // 128 x 16 bf16, 32B rows
    __shared__ __align__(16) unsigned char sAlo[4096];
    __shared__ __align__(16) unsigned char sBhi[8192];   // 16 x 128 bf16, 256B rows
    __shared__ __align__(16) unsigned char sBlo[8192];

    const int tid = threadIdx.x;
    const int wid = tid >> 5, lane = tid & 31;
    const int warp_m = wid & 1;        // 2 x 64 rows
    const int warp_n = wid >> 1;       // 4 x 32 cols
    const int m0 = blockIdx.x * 128;

    float acc[4][4][4];
#pragma unroll
    for (int mt = 0; mt < 4; mt++)
#pragma unroll
        for (int nt = 0; nt < 4; nt++)
#pragma unroll
            for (int q = 0; q < 4; q++) acc[mt][nt][q] = 0.f;

    const int a_row  = tid >> 1;          // 0..127
    const int a_half = tid & 1;           // 8 floats each
    const int arow_g = m0 + a_row;
    const int b_kr   = tid >> 4;          // 0..15
    const int b_n0   = (tid & 15) * 8;

    const uint32_t uAhi = smem_u32(sAhi), uAlo = smem_u32(sAlo);
    const uint32_t uBhi = smem_u32(sBhi), uBlo = smem_u32(sBlo);

    uint32_t a_addr[4], b_addr[2];
#pragma unroll
    for (int mt = 0; mt < 4; mt++) {
        int row = warp_m * 64 + mt * 16 + (lane & 15);
        uint32_t byte = (uint32_t)row * 32 + (uint32_t)(lane >> 4) * 16;
        byte ^= ((uint32_t)(row >> 2) & 1u) << 4;
        a_addr[mt] = byte;
    }
#pragma unroll
    for (int p = 0; p < 2; p++) {
        int kk = lane & 15;
        int ncol = warp_n * 32 + p * 16 + ((lane >> 4) << 3);
        uint32_t byte = (uint32_t)kk * 256 + (uint32_t)ncol * 2;
        byte ^= ((uint32_t)kk & 7u) << 4;
        b_addr[p] = byte;
    }

    uint32_t sa_byte = (uint32_t)a_row * 32 + (uint32_t)a_half * 16;
    sa_byte ^= ((uint32_t)(a_row >> 2) & 1u) << 4;
    uint32_t sb_byte = (uint32_t)b_kr * 256 + (uint32_t)b_n0 * 2;
    sb_byte ^= ((uint32_t)b_kr & 7u) << 4;

    for (int k0 = 0; k0 < K; k0 += 16) {
        // ---- stage A tile (fp32 -> bf16 hi/lo, optional relu) ----
        {
            float f[8];
            if (arow_g < M) {
                const float* ap = A + (size_t)arow_g * K + k0 + a_half * 8;
                float4 v0 = *(const float4*)ap;
                float4 v1 = *(const float4*)(ap + 4);
                f[0] = v0.x; f[1] = v0.y; f[2] = v0.z; f[3] = v0.w;
                f[4] = v1.x; f[5] = v1.y; f[6] = v1.z; f[7] = v1.w;
                if (RELU_IN) {
#pragma unroll
                    for (int i = 0; i < 8; i++) f[i] = fmaxf(f[i], 0.f);
                }
            } else {
#pragma unroll
                for (int i = 0; i < 8; i++) f[i] = 0.f;
            }
            uint4 hi, lo;
            cvt8(f, hi, lo);
            *(uint4*)(sAhi + sa_byte) = hi;
            *(uint4*)(sAlo + sa_byte) = lo;
        }
        // ---- stage B tile ----
        {
            const float* bp = B + (size_t)(k0 + b_kr) * HID + b_n0;
            float f[8];
            float4 v0 = *(const float4*)bp;
            float4 v1 = *(const float4*)(bp + 4);
            f[0] = v0.x; f[1] = v0.y; f[2] = v0.z; f[3] = v0.w;
            f[4] = v1.x; f[5] = v1.y; f[6] = v1.z; f[7] = v1.w;
            uint4 hi, lo;
            cvt8(f, hi, lo);
            *(uint4*)(sBhi + sb_byte) = hi;
            *(uint4*)(sBlo + sb_byte) = lo;
        }
        __syncthreads();

        uint32_t ah[4][4], al[4][4], bh[2][4], bl[2][4];
#pragma unroll
        for (int mt = 0; mt < 4; mt++) {
            ldsm_x4(ah[mt], uAhi + a_addr[mt]);
            ldsm_x4(al[mt], uAlo + a_addr[mt]);
        }
#pragma unroll
        for (int p = 0; p < 2; p++) {
            ldsm_x4_t(bh[p], uBhi + b_addr[p]);
            ldsm_x4_t(bl[p], uBlo + b_addr[p]);
        }
#pragma unroll
        for (int mt = 0; mt < 4; mt++) {
#pragma unroll
            for (int nt = 0; nt < 4; nt++) {
                const int p = nt >> 1, w = (nt & 1) * 2;
                uint32_t bhx[2] = {bh[p][w], bh[p][w + 1]};
                uint32_t blx[2] = {bl[p][w], bl[p][w + 1]};
                mma_bf16(acc[mt][nt], ah[mt], bhx);
                mma_bf16(acc[mt][nt], ah[mt], blx);
                mma_bf16(acc[mt][nt], al[mt], bhx);
            }
        }
        __syncthreads();
    }

    // ---- epilogue ----
#pragma unroll
    for (int nt = 0; nt < 4; nt++) {
        int cc = warp_n * 32 + nt * 8 + (lane & 3) * 2;
        float b0 = 0.f, b1 = 0.f;
        if (BIAS) { b0 = __ldg(&bias[cc]); b1 = __ldg(&bias[cc + 1]); }
#pragma unroll
        for (int mt = 0; mt < 4; mt++) {
            int rg = m0 + warp_m * 64 + mt * 16 + (lane >> 2);
            float o0 = acc[mt][nt][0] + b0, o1 = acc[mt][nt][1] + b1;
            float o2 = acc[mt][nt][2] + b0, o3 = acc[mt][nt][3] + b1;
            if (RELU_EPI) {
                o0 = fmaxf(o0, 0.f); o1 = fmaxf(o1, 0.f);
                o2 = fmaxf(o2, 0.f); o3 = fmaxf(o3, 0.f);
            }
            if (rg < M)     *(float2*)(C + (size_t)rg * HID + cc)       = make_float2(o0, o1);
            if (rg + 8 < M) *(float2*)(C + (size_t)(rg + 8) * HID + cc) = make_float2(o2, o3);
        }
    }
}

// ---------------- ragged masked mean: one warp per row ----------------
__global__ void k_rowmean(const float* __restrict__ h, const int* __restrict__ ridx,
                          const unsigned char* __restrict__ rmask, float* __restrict__ outm) {
    long long gtid = (long long)blockIdx.x * blockDim.x + threadIdx.x;
    long long w = gtid >> 5;
    if (w >= NR) return;
    int lane = threadIdx.x & 31;
    const int is_int = g_mask_is_int;
    const int* rmask_i = (const int*)rmask;
    float4 acc = make_float4(0.f, 0.f, 0.f, 0.f);
    float cnt = 0.f;
#pragma unroll
    for (int f = 0; f < FF; f++) {
        bool on = is_int ? (__ldg(&rmask_i[w * FF + f]) != 0) : (rmask[w * FF + f] != 0);
        if (on) {
            int idx = __ldg(&ridx[w * FF + f]);
            float4 v = __ldg((const float4*)(h + (size_t)idx * HID) + lane);
            acc.x += v.x; acc.y += v.y; acc.z += v.z; acc.w += v.w;
            cnt += 1.f;
        }
    }
    float inv = 1.f / fmaxf(cnt, 1.f);
    acc.x *= inv; acc.y *= inv; acc.z *= inv; acc.w *= inv;
    *((float4*)(outm + (size_t)w * HID) + lane) = acc;
}

// ---------------- final head: [NR][128] @ [128][10] + b (fp32) ----------------
__global__ void k_head(const float* __restrict__ X, const float* __restrict__ W,
                       const float* __restrict__ b, float* __restrict__ out) {
    long long t = (long long)blockIdx.x * blockDim.x + threadIdx.x;
    int row = (int)(t >> 4);
    int c = (int)(t & 15);
    if (row >= NR || c >= NC) return;
    const float* x = X + (size_t)row * HID;
    float acc = b[c];
#pragma unroll
    for (int k = 0; k < HID; k++) acc += x[k] * __ldg(&W[k * NC + c]);
    out[(size_t)row * NC + c] = acc;
}

// ---------------- launch ----------------
extern "C" void kernel_launch(void* const* d_in, const int* in_sizes, int n_in,
                              void* d_out, int out_size) {
    const float* node_feats = (const float*)d_in[0];
    const int*   edges_src  = (const int*)  d_in[1];
    const int*   edges_dst  = (const int*)  d_in[2];
    const int*   row_idx    = (const int*)  d_in[3];
    const unsigned char* row_mask = (const unsigned char*)d_in[4];
    const float* W_in = (const float*)d_in[5];
    const float* b_in = (const float*)d_in[6];
    const float* W1   = (const float*)d_in[7];
    const float* b1   = (const float*)d_in[8];
    const float* W2   = (const float*)d_in[9];
    const float* b2   = (const float*)d_in[10];
    const float* Wm1  = (const float*)d_in[11];
    const float* bm1  = (const float*)d_in[12];
    const float* Wm2  = (const float*)d_in[13];
    const float* bm2  = (const float*)d_in[14];
    const float* Wm3  = (const float*)d_in[15];
    const float* bm3  = (const float*)d_in[16];
    float* out = (float*)d_out;

    float *p_h0, *p_acc1, *p_acc2, *p_z, *p_dego, *p_degi, *p_ns, *p_nd,
          *p_mean, *p_x1, *p_x2;
    cudaGetSymbolAddress((void**)&p_h0,   g_h0);
    cudaGetSymbolAddress((void**)&p_acc1, g_acc1);
    cudaGetSymbolAddress((void**)&p_acc2, g_acc2);
    cudaGetSymbolAddress((void**)&p_z,    g_z);
    cudaGetSymbolAddress((void**)&p_dego, g_deg_out);
    cudaGetSymbolAddress((void**)&p_degi, g_deg_in);
    cudaGetSymbolAddress((void**)&p_ns,   g_norm_s);
    cudaGetSymbolAddress((void**)&p_nd,   g_norm_d);
    cudaGetSymbolAddress((void**)&p_mean, g_mean);
    cudaGetSymbolAddress((void**)&p_x1,   g_x1);
    cudaGetSymbolAddress((void**)&p_x2,   g_x2);

    const long long deg4 = (long long)RR * NN / 4;
    const int gb_nn = (NN + 127) / 128;   // 297
    const int gb_nr = (NR + 127) / 128;   // 469
    const unsigned agg_blocks = (unsigned)(((long long)EE * 32 + 255) / 256);
    const int bias_blocks = (int)(((long long)NN * HID + 255) / 256);

    // mask dtype detection
    k_detect_mask<<<1, 256>>>(row_mask);

    // degrees + norms
    k_zero4<<<2048, 256>>>((float4*)p_dego, deg4);
    k_zero4<<<2048, 256>>>((float4*)p_degi, deg4);
    k_deg<<<(RR * EE + 255) / 256, 256>>>(edges_src, edges_dst);
    k_norms<<<(RR * NN + 255) / 256, 256>>>();

    // input linear + relu
    k_tmma<true, false, true><<<gb_nn, 256>>>(node_feats, W_in, b_in, p_h0, NN, IND);

    // ---- RGCN layer 1: acc1 = sum_r scatter(h0 @ W1_r, ns_r, nd_r) + sum_r b1_r
    k_bias_init<<<bias_blocks, 256>>>(b1, p_acc1);
    for (int r = 0; r < RR; r++) {
        k_tmma<false, false, false><<<gb_nn, 256>>>(
            p_h0, W1 + (size_t)r * HID * HID, nullptr, p_z, NN, HID);
        k_agg3<<<agg_blocks, 256>>>(p_z, edges_src + (size_t)r * EE,
                                    edges_dst + (size_t)r * EE,
                                    p_ns + (size_t)r * NN, p_nd + (size_t)r * NN, p_acc1);
    }

    // ---- RGCN layer 2: relu folded into the A-loader of the relation GEMMs
    k_bias_init<<<bias_blocks, 256>>>(b2, p_acc2);
    for (int r = 0; r < RR; r++) {
        k_tmma<false, true, false><<<gb_nn, 256>>>(
            p_acc1, W2 + (size_t)r * HID * HID, nullptr, p_z, NN, HID);
        k_agg3<<<agg_blocks, 256>>>(p_z, edges_src + (size_t)r * EE,
                                    edges_dst + (size_t)r * EE,
                                    p_ns + (size_t)r * NN, p_nd + (size_t)r * NN, p_acc2);
    }

    // ragged masked mean over acc2 (= h2, no relu)
    {
        long long nt = (long long)NR * 32;
        k_rowmean<<<(unsigned)((nt + 255) / 256), 256>>>(p_acc2, row_idx, row_mask, p_mean);
    }

    // MLP head
    k_tmma<true, false, true><<<gb_nr, 256>>>(p_mean, Wm1, bm1, p_x1, NR, HID);
    k_tmma<true, false, true><<<gb_nr, 256>>>(p_x1,  Wm2, bm2, p_x2, NR, HID);
    k_head<<<(NR * 16 + 255) / 256, 256>>>(p_x2, Wm3, bm3, out);

    (void)in_sizes; (void)n_in; (void)out_size;
}

// round 13
// speedup vs baseline: 1.9256x; 1.1051x over previous
#include <cuda_runtime.h>
#include <cuda_bf16.h>
#include <cstdint>

// ---------------- problem constants ----------------
constexpr int NN  = 38000;   // nodes
constexpr int IND = 64;      // input dim
constexpr int HID = 128;
constexpr int RR  = 8;       // relations
constexpr int EE  = 200000;  // edges per relation
constexpr int NR  = 60000;   // rows
constexpr int FF  = 19;      // features per row
constexpr int NC  = 10;      // classes

// ---------------- device scratch (static, no allocation) ----------------
__device__ float g_h0[(size_t)NN * HID];     // relu(X @ W_in + b_in)
__device__ float g_acc1[(size_t)NN * HID];   // layer-1 accumulator (pre-relu)
__device__ float g_acc2[(size_t)NN * HID];   // layer-2 accumulator (= h2)
__device__ float g_z[(size_t)NN * HID];      // per-relation transformed feats
__device__ int   g_hist_out[RR * NN];        // out-degree (by src)
__device__ int   g_hist_in[RR * NN];         // in-degree (by dst)
__device__ float g_norm_s[RR * NN];
__device__ float g_norm_d[RR * NN];
__device__ int   g_indptr[RR * (NN + 1)];    // CSR row pointers (by dst)
__device__ int   g_cursor[RR * NN];          // fill cursors
__device__ int   g_csr_src[(size_t)RR * EE]; // src node per CSR slot
__device__ float g_mean[(size_t)NR * HID];
__device__ float g_x1[(size_t)NR * HID];
__device__ float g_x2[(size_t)NR * HID];
__device__ int   g_mask_is_int;

// ---------------- helpers ----------------
__device__ __forceinline__ uint32_t smem_u32(const void* p) {
    uint32_t a;
    asm("{ .reg .u64 t; cvta.to.shared.u64 t, %1; cvt.u32.u64 %0, t; }" : "=r"(a) : "l"(p));
    return a;
}

// convert 8 fp32 -> packed bf16 hi (uint4) + residual lo (uint4)
__device__ __forceinline__ void cvt8(const float* f, uint4& hi, uint4& lo) {
    unsigned h[4], l[4];
#pragma unroll
    for (int i = 0; i < 4; i++) {
        float f0 = f[2 * i], f1 = f[2 * i + 1];
        __nv_bfloat16 b0 = __float2bfloat16(f0), b1 = __float2bfloat16(f1);
        __nv_bfloat16 c0 = __float2bfloat16(f0 - __bfloat162float(b0));
        __nv_bfloat16 c1 = __float2bfloat16(f1 - __bfloat162float(b1));
        h[i] = (unsigned)__bfloat16_as_ushort(b0) | ((unsigned)__bfloat16_as_ushort(b1) << 16);
        l[i] = (unsigned)__bfloat16_as_ushort(c0) | ((unsigned)__bfloat16_as_ushort(c1) << 16);
    }
    hi = make_uint4(h[0], h[1], h[2], h[3]);
    lo = make_uint4(l[0], l[1], l[2], l[3]);
}

__device__ __forceinline__ void ldsm_x4(uint32_t* r, uint32_t addr) {
    asm volatile("ldmatrix.sync.aligned.m8n8.x4.shared.b16 {%0,%1,%2,%3}, [%4];"
                 : "=r"(r[0]), "=r"(r[1]), "=r"(r[2]), "=r"(r[3]) : "r"(addr));
}
__device__ __forceinline__ void ldsm_x4_t(uint32_t* r, uint32_t addr) {
    asm volatile("ldmatrix.sync.aligned.m8n8.x4.trans.shared.b16 {%0,%1,%2,%3}, [%4];"
                 : "=r"(r[0]), "=r"(r[1]), "=r"(r[2]), "=r"(r[3]) : "r"(addr));
}
__device__ __forceinline__ void mma_bf16(float* c, const uint32_t* a, const uint32_t* b) {
    asm volatile("mma.sync.aligned.m16n8k16.row.col.f32.bf16.bf16.f32 "
                 "{%0,%1,%2,%3}, {%4,%5,%6,%7}, {%8,%9}, {%0,%1,%2,%3};"
                 : "+f"(c[0]), "+f"(c[1]), "+f"(c[2]), "+f"(c[3])
                 : "r"(a[0]), "r"(a[1]), "r"(a[2]), "r"(a[3]), "r"(b[0]), "r"(b[1]));
}

// ---------------- zero ----------------
__global__ void k_zero4(float4* p, long long n4) {
    long long i = (long long)blockIdx.x * blockDim.x + threadIdx.x;
    long long stride = (long long)gridDim.x * blockDim.x;
    float4 z = make_float4(0.f, 0.f, 0.f, 0.f);
    for (; i < n4; i += stride) p[i] = z;
}

// ---------------- mask dtype detection (bool stored as u8 vs i32) ----------
__global__ void k_detect_mask(const unsigned char* __restrict__ m) {
    __shared__ int cnt;
    if (threadIdx.x == 0) cnt = 0;
    __syncthreads();
    int local = 0;
    for (int i = threadIdx.x; i < 65536; i += blockDim.x) local += (m[i] != 0);
    atomicAdd(&cnt, local);
    __syncthreads();
    if (threadIdx.x == 0) g_mask_is_int = (cnt < 16384) ? 1 : 0;
}

// ---------------- CSR build ----------------
__global__ void k_hist(const int* __restrict__ src, const int* __restrict__ dst) {
    long long i = (long long)blockIdx.x * blockDim.x + threadIdx.x;
    if (i >= (long long)RR * EE) return;
    int r = (int)(i / EE);
    atomicAdd(&g_hist_out[r * NN + src[i]], 1);
    atomicAdd(&g_hist_in [r * NN + dst[i]], 1);
}

__global__ void k_norms() {
    int i = blockIdx.x * blockDim.x + threadIdx.x;
    if (i >= RR * NN) return;
    g_norm_s[i] = rsqrtf(fmaxf((float)g_hist_out[i], 1.f));
    g_norm_d[i] = rsqrtf(fmaxf((float)g_hist_in [i], 1.f));
}

// one block per relation: exclusive prefix sum of in-degree -> indptr + cursor
__global__ void k_scan() {
    const int r = blockIdx.x;
    const int t = threadIdx.x;
    __shared__ int buf[1024];
    __shared__ int carry;
    if (t == 0) carry = 0;
    __syncthreads();
    for (int base = 0; base < NN; base += 1024) {
        int v = (base + t < NN) ? g_hist_in[r * NN + base + t] : 0;
        buf[t] = v;
        __syncthreads();
#pragma unroll
        for (int off = 1; off < 1024; off <<= 1) {
            int x = (t >= off) ? buf[t - off] : 0;
            __syncthreads();
            buf[t] += x;
            __syncthreads();
        }
        int c = carry;
        if (base + t < NN) {
            int excl = c + buf[t] - v;
            g_indptr[r * (NN + 1) + base + t] = excl;
            g_cursor[r * NN + base + t] = excl;
        }
        __syncthreads();
        if (t == 1023) carry = c + buf[1023];
        __syncthreads();
    }
    if (t == 0) g_indptr[r * (NN + 1) + NN] = carry;
}

__global__ void k_fill(const int* __restrict__ src, const int* __restrict__ dst) {
    long long i = (long long)blockIdx.x * blockDim.x + threadIdx.x;
    if (i >= (long long)RR * EE) return;
    int r = (int)(i / EE);
    int d = dst[i];
    int pos = atomicAdd(&g_cursor[r * NN + d], 1);
    g_csr_src[(size_t)r * EE + pos] = src[i];
}

// ---------------- accumulator init: acc[n][c] = sum_r b[r][c] ----------------
__global__ void k_bias_init(const float* __restrict__ b, float* __restrict__ acc) {
    long long i = (long long)blockIdx.x * blockDim.x + threadIdx.x;
    if (i >= (long long)NN * HID) return;
    int c = (int)(i & (HID - 1));
    float s = 0.f;
#pragma unroll
    for (int r = 0; r < RR; r++) s += __ldg(&b[r * HID + c]);
    acc[i] = s;
}

// ---------------- CSR gather: acc[d] += nd[d] * sum_{e:dst=d} ns[src]*z[src] -----
// one warp per destination node; no atomics (warp owns its acc row).
__global__ void k_gather(const float* __restrict__ z,
                         const int* __restrict__ csr_src, const int* __restrict__ indptr,
                         const float* __restrict__ ns_r, const float* __restrict__ nd_r,
                         float* __restrict__ acc) {
    int gw = (int)(((long long)blockIdx.x * blockDim.x + threadIdx.x) >> 5);
    if (gw >= NN) return;
    int lane = threadIdx.x & 31;
    int n0 = __ldg(&indptr[gw]);
    int n1 = __ldg(&indptr[gw + 1]);
    if (n0 == n1) return;
    float4 s4 = make_float4(0.f, 0.f, 0.f, 0.f);
    for (int e = n0; e < n1; e++) {
        int s = __ldg(&csr_src[e]);
        float w = __ldg(&ns_r[s]);
        float4 v = __ldg((const float4*)(z + (size_t)s * HID) + lane);
        s4.x += w * v.x; s4.y += w * v.y; s4.z += w * v.z; s4.w += w * v.w;
    }
    float nd = __ldg(&nd_r[gw]);
    float4* ap = (float4*)(acc + (size_t)gw * HID) + lane;
    float4 a = *ap;
    a.x += nd * s4.x; a.y += nd * s4.y; a.z += nd * s4.z; a.w += nd * s4.w;
    *ap = a;
}

// ---------------- tensor-core split-bf16 GEMM ----------------
// C[M][128] = epi(pre(A)[M][K] @ B[K][128] [+ bias]); fp32 in/out, internally
// split bf16 (hi+lo, 3 mma passes) with fp32 accumulation.
// BM=128, BN=128, BK=16, 256 threads (8 warps: 2x4), 4x4 m16n8k16 tiles/warp.
template <bool RELU_EPI, bool RELU_IN, bool BIAS>
__global__ __launch_bounds__(256, 2)
void k_tmma(const float* __restrict__ A, const float* __restrict__ B,
            const float* __restrict__ bias, float* __restrict__ C,
            int M, int K) {
    __shared__ __align__(16) unsigned char sAhi[4096];   // 128 x 16 bf16, 32B rows
    __shared__ __align__(16) unsigned char sAlo[4096];
    __shared__ __align__(16) unsigned char sBhi[8192];   // 16 x 128 bf16, 256B rows
    __shared__ __align__(16) unsigned char sBlo[8192];

    const int tid = threadIdx.x;
    const int wid = tid >> 5, lane = tid & 31;
    const int warp_m = wid & 1;        // 2 x 64 rows
    const int warp_n = wid >> 1;       // 4 x 32 cols
    const int m0 = blockIdx.x * 128;

    float acc[4][4][4];
#pragma unroll
    for (int mt = 0; mt < 4; mt++)
#pragma unroll
        for (int nt = 0; nt < 4; nt++)
#pragma unroll
            for (int q = 0; q < 4; q++) acc[mt][nt][q] = 0.f;

    const int a_row  = tid >> 1;          // 0..127
    const int a_half = tid & 1;           // 8 floats each
    const int arow_g = m0 + a_row;
    const int b_kr   = tid >> 4;          // 0..15
    const int b_n0   = (tid & 15) * 8;

    const uint32_t uAhi = smem_u32(sAhi), uAlo = smem_u32(sAlo);
    const uint32_t uBhi = smem_u32(sBhi), uBlo = smem_u32(sBlo);

    uint32_t a_addr[4], b_addr[2];
#pragma unroll
    for (int mt = 0; mt < 4; mt++) {
        int row = warp_m * 64 + mt * 16 + (lane & 15);
        uint32_t byte = (uint32_t)row * 32 + (uint32_t)(lane >> 4) * 16;
        byte ^= ((uint32_t)(row >> 2) & 1u) << 4;
        a_addr[mt] = byte;
    }
#pragma unroll
    for (int p = 0; p < 2; p++) {
        int kk = lane & 15;
        int ncol = warp_n * 32 + p * 16 + ((lane >> 4) << 3);
        uint32_t byte = (uint32_t)kk * 256 + (uint32_t)ncol * 2;
        byte ^= ((uint32_t)kk & 7u) << 4;
        b_addr[p] = byte;
    }

    uint32_t sa_byte = (uint32_t)a_row * 32 + (uint32_t)a_half * 16;
    sa_byte ^= ((uint32_t)(a_row >> 2) & 1u) << 4;
    uint32_t sb_byte = (uint32_t)b_kr * 256 + (uint32_t)b_n0 * 2;
    sb_byte ^= ((uint32_t)b_kr & 7u) << 4;

    for (int k0 = 0; k0 < K; k0 += 16) {
        // ---- stage A tile (fp32 -> bf16 hi/lo, optional relu) ----
        {
            float f[8];
            if (arow_g < M) {
                const float* ap = A + (size_t)arow_g * K + k0 + a_half * 8;
                float4 v0 = *(const float4*)ap;
                float4 v1 = *(const float4*)(ap + 4);
                f[0] = v0.x; f[1] = v0.y; f[2] = v0.z; f[3] = v0.w;
                f[4] = v1.x; f[5] = v1.y; f[6] = v1.z; f[7] = v1.w;
                if (RELU_IN) {
#pragma unroll
                    for (int i = 0; i < 8; i++) f[i] = fmaxf(f[i], 0.f);
                }
            } else {
#pragma unroll
                for (int i = 0; i < 8; i++) f[i] = 0.f;
            }
            uint4 hi, lo;
            cvt8(f, hi, lo);
            *(uint4*)(sAhi + sa_byte) = hi;
            *(uint4*)(sAlo + sa_byte) = lo;
        }
        // ---- stage B tile ----
        {
            const float* bp = B + (size_t)(k0 + b_kr) * HID + b_n0;
            float f[8];
            float4 v0 = *(const float4*)bp;
            float4 v1 = *(const float4*)(bp + 4);
            f[0] = v0.x; f[1] = v0.y; f[2] = v0.z; f[3] = v0.w;
            f[4] = v1.x; f[5] = v1.y; f[6] = v1.z; f[7] = v1.w;
            uint4 hi, lo;
            cvt8(f, hi, lo);
            *(uint4*)(sBhi + sb_byte) = hi;
            *(uint4*)(sBlo + sb_byte) = lo;
        }
        __syncthreads();

        uint32_t ah[4][4], al[4][4], bh[2][4], bl[2][4];
#pragma unroll
        for (int mt = 0; mt < 4; mt++) {
            ldsm_x4(ah[mt], uAhi + a_addr[mt]);
            ldsm_x4(al[mt], uAlo + a_addr[mt]);
        }
#pragma unroll
        for (int p = 0; p < 2; p++) {
            ldsm_x4_t(bh[p], uBhi + b_addr[p]);
            ldsm_x4_t(bl[p], uBlo + b_addr[p]);
        }
#pragma unroll
        for (int mt = 0; mt < 4; mt++) {
#pragma unroll
            for (int nt = 0; nt < 4; nt++) {
                const int p = nt >> 1, w = (nt & 1) * 2;
                uint32_t bhx[2] = {bh[p][w], bh[p][w + 1]};
                uint32_t blx[2] = {bl[p][w], bl[p][w + 1]};
                mma_bf16(acc[mt][nt], ah[mt], bhx);
                mma_bf16(acc[mt][nt], ah[mt], blx);
                mma_bf16(acc[mt][nt], al[mt], bhx);
            }
        }
        __syncthreads();
    }

    // ---- epilogue ----
#pragma unroll
    for (int nt = 0; nt < 4; nt++) {
        int cc = warp_n * 32 + nt * 8 + (lane & 3) * 2;
        float b0 = 0.f, b1 = 0.f;
        if (BIAS) { b0 = __ldg(&bias[cc]); b1 = __ldg(&bias[cc + 1]); }
#pragma unroll
        for (int mt = 0; mt < 4; mt++) {
            int rg = m0 + warp_m * 64 + mt * 16 + (lane >> 2);
            float o0 = acc[mt][nt][0] + b0, o1 = acc[mt][nt][1] + b1;
            float o2 = acc[mt][nt][2] + b0, o3 = acc[mt][nt][3] + b1;
            if (RELU_EPI) {
                o0 = fmaxf(o0, 0.f); o1 = fmaxf(o1, 0.f);
                o2 = fmaxf(o2, 0.f); o3 = fmaxf(o3, 0.f);
            }
            if (rg < M)     *(float2*)(C + (size_t)rg * HID + cc)       = make_float2(o0, o1);
            if (rg + 8 < M) *(float2*)(C + (size_t)(rg + 8) * HID + cc) = make_float2(o2, o3);
        }
    }
}

// ---------------- ragged masked mean: one warp per row ----------------
__global__ void k_rowmean(const float* __restrict__ h, const int* __restrict__ ridx,
                          const unsigned char* __restrict__ rmask, float* __restrict__ outm) {
    long long gtid = (long long)blockIdx.x * blockDim.x + threadIdx.x;
    long long w = gtid >> 5;
    if (w >= NR) return;
    int lane = threadIdx.x & 31;
    const int is_int = g_mask_is_int;
    const int* rmask_i = (const int*)rmask;
    float4 acc = make_float4(0.f, 0.f, 0.f, 0.f);
    float cnt = 0.f;
#pragma unroll
    for (int f = 0; f < FF; f++) {
        bool on = is_int ? (__ldg(&rmask_i[w * FF + f]) != 0) : (rmask[w * FF + f] != 0);
        if (on) {
            int idx = __ldg(&ridx[w * FF + f]);
            float4 v = __ldg((const float4*)(h + (size_t)idx * HID) + lane);
            acc.x += v.x; acc.y += v.y; acc.z += v.z; acc.w += v.w;
            cnt += 1.f;
        }
    }
    float inv = 1.f / fmaxf(cnt, 1.f);
    acc.x *= inv; acc.y *= inv; acc.z *= inv; acc.w *= inv;
    *((float4*)(outm + (size_t)w * HID) + lane) = acc;
}

// ---------------- final head: [NR][128] @ [128][10] + b (fp32) ----------------
__global__ void k_head(const float* __restrict__ X, const float* __restrict__ W,
                       const float* __restrict__ b, float* __restrict__ out) {
    long long t = (long long)blockIdx.x * blockDim.x + threadIdx.x;
    int row = (int)(t >> 4);
    int c = (int)(t & 15);
    if (row >= NR || c >= NC) return;
    const float* x = X + (size_t)row * HID;
    float acc = b[c];
#pragma unroll
    for (int k = 0; k < HID; k++) acc += x[k] * __ldg(&W[k * NC + c]);
    out[(size_t)row * NC + c] = acc;
}

// ---------------- launch ----------------
extern "C" void kernel_launch(void* const* d_in, const int* in_sizes, int n_in,
                              void* d_out, int out_size) {
    const float* node_feats = (const float*)d_in[0];
    const int*   edges_src  = (const int*)  d_in[1];
    const int*   edges_dst  = (const int*)  d_in[2];
    const int*   row_idx    = (const int*)  d_in[3];
    const unsigned char* row_mask = (const unsigned char*)d_in[4];
    const float* W_in = (const float*)d_in[5];
    const float* b_in = (const float*)d_in[6];
    const float* W1   = (const float*)d_in[7];
    const float* b1   = (const float*)d_in[8];
    const float* W2   = (const float*)d_in[9];
    const float* b2   = (const float*)d_in[10];
    const float* Wm1  = (const float*)d_in[11];
    const float* bm1  = (const float*)d_in[12];
    const float* Wm2  = (const float*)d_in[13];
    const float* bm2  = (const float*)d_in[14];
    const float* Wm3  = (const float*)d_in[15];
    const float* bm3  = (const float*)d_in[16];
    float* out = (float*)d_out;

    float *p_h0, *p_acc1, *p_acc2, *p_z, *p_ns, *p_nd, *p_mean, *p_x1, *p_x2;
    int *p_ho, *p_hi, *p_ip, *p_cs;
    cudaGetSymbolAddress((void**)&p_h0,   g_h0);
    cudaGetSymbolAddress((void**)&p_acc1, g_acc1);
    cudaGetSymbolAddress((void**)&p_acc2, g_acc2);
    cudaGetSymbolAddress((void**)&p_z,    g_z);
    cudaGetSymbolAddress((void**)&p_ho,   g_hist_out);
    cudaGetSymbolAddress((void**)&p_hi,   g_hist_in);
    cudaGetSymbolAddress((void**)&p_ns,   g_norm_s);
    cudaGetSymbolAddress((void**)&p_nd,   g_norm_d);
    cudaGetSymbolAddress((void**)&p_ip,   g_indptr);
    cudaGetSymbolAddress((void**)&p_cs,   g_csr_src);
    cudaGetSymbolAddress((void**)&p_mean, g_mean);
    cudaGetSymbolAddress((void**)&p_x1,   g_x1);
    cudaGetSymbolAddress((void**)&p_x2,   g_x2);

    const long long deg4 = (long long)RR * NN / 4;
    const int gb_nn = (NN + 127) / 128;   // 297
    const int gb_nr = (NR + 127) / 128;   // 469
    const unsigned gat_blocks = (unsigned)(((long long)NN * 32 + 255) / 256);
    const int bias_blocks = (int)(((long long)NN * HID + 255) / 256);

    // mask dtype detection
    k_detect_mask<<<1, 256>>>(row_mask);

    // ---- CSR build (reused by both layers) + degrees/norms ----
    k_zero4<<<1024, 256>>>((float4*)p_ho, deg4);
    k_zero4<<<1024, 256>>>((float4*)p_hi, deg4);
    k_hist<<<(RR * EE + 255) / 256, 256>>>(edges_src, edges_dst);
    k_norms<<<(RR * NN + 255) / 256, 256>>>();
    k_scan<<<RR, 1024>>>();
    k_fill<<<(RR * EE + 255) / 256, 256>>>(edges_src, edges_dst);

    // input linear + relu
    k_tmma<true, false, true><<<gb_nn, 256>>>(node_feats, W_in, b_in, p_h0, NN, IND);

    // ---- RGCN layer 1: acc1 = sum_r gather(h0 @ W1_r) + sum_r b1_r
    k_bias_init<<<bias_blocks, 256>>>(b1, p_acc1);
    for (int r = 0; r < RR; r++) {
        k_tmma<false, false, false><<<gb_nn, 256>>>(
            p_h0, W1 + (size_t)r * HID * HID, nullptr, p_z, NN, HID);
        k_gather<<<gat_blocks, 256>>>(p_z, p_cs + (size_t)r * EE, p_ip + r * (NN + 1),
                                      p_ns + (size_t)r * NN, p_nd + (size_t)r * NN, p_acc1);
    }

    // ---- RGCN layer 2: relu folded into the A-loader of the relation GEMMs
    k_bias_init<<<bias_blocks, 256>>>(b2, p_acc2);
    for (int r = 0; r < RR; r++) {
        k_tmma<false, true, false><<<gb_nn, 256>>>(
            p_acc1, W2 + (size_t)r * HID * HID, nullptr, p_z, NN, HID);
        k_gather<<<gat_blocks, 256>>>(p_z, p_cs + (size_t)r * EE, p_ip + r * (NN + 1),
                                      p_ns + (size_t)r * NN, p_nd + (size_t)r * NN, p_acc2);
    }

    // ragged masked mean over acc2 (= h2, no relu)
    {
        long long nt = (long long)NR * 32;
        k_rowmean<<<(unsigned)((nt + 255) / 256), 256>>>(p_acc2, row_idx, row_mask, p_mean);
    }

    // MLP head
    k_tmma<true, false, true><<<gb_nr, 256>>>(p_mean, Wm1, bm1, p_x1, NR, HID);
    k_tmma<true, false, true><<<gb_nr, 256>>>(p_x1,  Wm2, bm2, p_x2, NR, HID);
    k_head<<<(NR * 16 + 255) / 256, 256>>>(p_x2, Wm3, bm3, out);

    (void)in_sizes; (void)n_in; (void)out_size;
}